// round 1
// baseline (speedup 1.0000x reference)
#include <cuda_runtime.h>

#define T_TOKENS 4096
#define DIM      2048
#define NEXP     8
#define TOPK     2
#define HDIM     1024
#define HSDIM    2048
#define NSLOTS   (T_TOKENS * TOPK)

#define BM 128
#define BN 128
#define BKK 16
#define TM 8
#define TN 8
#define NTHREADS 256

// ---------------- scratch (device globals; no allocation allowed) ----------------
__device__ float g_hbuf[(size_t)NSLOTS * HDIM];    // routed h (weight-folded)  33.5 MB
__device__ float g_sh[(size_t)T_TOKENS * HSDIM];   // shared-expert h          33.5 MB
__device__ int   g_slot_token[NSLOTS];
__device__ float g_slot_w[NSLOTS];
__device__ int   g_counts[NEXP];
__device__ int   g_fill[NEXP];
__device__ int   g_offsets[NEXP + 1];
__device__ int   g_eidx[NSLOTS];
__device__ float g_topw[NSLOTS];

// ---------------- f32x2 packed-FMA helpers (Blackwell) ----------------
__device__ __forceinline__ double ffma2(double a, double b, double c) {
    double d;
    asm("fma.rn.f32x2 %0, %1, %2, %3;" : "=d"(d) : "d"(a), "d"(b), "d"(c));
    return d;
}
__device__ __forceinline__ double dup2(float a) {
    double d;
    asm("mov.b64 %0, {%1, %1};" : "=d"(d) : "f"(a));
    return d;
}
__device__ __forceinline__ float2 unpack2(double d) {
    float2 f;
    asm("mov.b64 {%0, %1}, %2;" : "=f"(f.x), "=f"(f.y) : "d"(d));
    return f;
}
__device__ __forceinline__ float silu_f(float g) {
    return g * (1.0f / (1.0f + __expf(-g)));
}

// ---------------- small kernels: routing ----------------
__global__ void zero_small_kernel() {
    int i = threadIdx.x;
    if (i < NEXP) { g_counts[i] = 0; g_fill[i] = 0; }
}

__global__ void router_kernel(const float* __restrict__ x, const float* __restrict__ rw) {
    int t = (blockIdx.x * blockDim.x + threadIdx.x) >> 5;
    int lane = threadIdx.x & 31;
    if (t >= T_TOKENS) return;
    const float* xr = x + (size_t)t * DIM;
    float lg[NEXP];
#pragma unroll
    for (int e = 0; e < NEXP; e++) lg[e] = 0.f;
    for (int d = lane; d < DIM; d += 32) {
        float xv = xr[d];
        const float* r = rw + (size_t)d * NEXP;
#pragma unroll
        for (int e = 0; e < NEXP; e++) lg[e] += xv * r[e];
    }
#pragma unroll
    for (int e = 0; e < NEXP; e++) {
#pragma unroll
        for (int o = 16; o; o >>= 1) lg[e] += __shfl_xor_sync(0xffffffffu, lg[e], o);
    }
    if (lane == 0) {
        float mx = lg[0];
#pragma unroll
        for (int e = 1; e < NEXP; e++) mx = fmaxf(mx, lg[e]);
        float p[NEXP];
#pragma unroll
        for (int e = 0; e < NEXP; e++) p[e] = __expf(lg[e] - mx);
        // top-2 (first-index wins ties, matching jax top_k)
        int i1 = 0;
#pragma unroll
        for (int e = 1; e < NEXP; e++) if (p[e] > p[i1]) i1 = e;
        int i2 = (i1 == 0) ? 1 : 0;
#pragma unroll
        for (int e = 0; e < NEXP; e++) if (e != i1 && p[e] > p[i2]) i2 = e;
        float w1 = p[i1], w2 = p[i2];
        float s = w1 + w2;
        w1 /= s; w2 /= s;
        g_eidx[2 * t] = i1; g_eidx[2 * t + 1] = i2;
        g_topw[2 * t] = w1; g_topw[2 * t + 1] = w2;
        atomicAdd(&g_counts[i1], 1);
        atomicAdd(&g_counts[i2], 1);
    }
}

__global__ void scan_kernel() {
    if (threadIdx.x == 0) {
        int acc = 0;
        for (int e = 0; e < NEXP; e++) { g_offsets[e] = acc; acc += g_counts[e]; }
        g_offsets[NEXP] = acc;
    }
}

__global__ void scatter_kernel() {
    int i = blockIdx.x * blockDim.x + threadIdx.x;
    if (i >= NSLOTS) return;
    int e = g_eidx[i];
    int pos = g_offsets[e] + atomicAdd(&g_fill[e], 1);
    g_slot_token[pos] = i >> 1;
    g_slot_w[pos] = g_topw[i];
}

// ---------------- fused gate/up GEMM (+SiLU) ----------------
// C[m,n] for two matmuls sharing A; epilogue h = silu(g)*u (* combine weight if ROUTED)
template <bool ROUTED>
__global__ __launch_bounds__(NTHREADS, 1)
void gateup_kernel(const float* __restrict__ X,
                   const float* __restrict__ Wg,
                   const float* __restrict__ Wu,
                   int N)  // HDIM (routed) or HSDIM (shared)
{
    int mtile = blockIdx.y, ntile = blockIdx.x;
    int expert = 0, start = 0, Me = T_TOKENS;
    if (ROUTED) {
        expert = blockIdx.z;
        start = g_offsets[expert];
        Me = g_offsets[expert + 1] - start;
        if (mtile * BM >= Me) return;
        Wg += (size_t)expert * DIM * N;
        Wu += (size_t)expert * DIM * N;
    }

    __shared__ float As[BKK][BM + 4];
    __shared__ float Bgs[BKK][BN];
    __shared__ float Bus[BKK][BN];

    int tid = threadIdx.x;
    int tx = tid & 15, ty = tid >> 4;

    // A loader: two rows per thread (rows tid/4 and tid/4+64), 4 cols each
    int arow0 = tid >> 2;
    int ac4 = (tid & 3) * 4;
    const float* arow_ptr[2];
#pragma unroll
    for (int it = 0; it < 2; it++) {
        int r = arow0 + it * 64;
        int rr = mtile * BM + r;
        if (rr >= Me) rr = Me - 1;              // clamp padding rows
        int gr = ROUTED ? g_slot_token[start + rr] : rr;
        arow_ptr[it] = X + (size_t)gr * DIM;
    }
    int brow0 = tid >> 5;
    int bc = (tid & 31) * 4;

    double accg[TM][TN / 2];
    double accu[TM][TN / 2];
#pragma unroll
    for (int i = 0; i < TM; i++)
#pragma unroll
        for (int j = 0; j < TN / 2; j++) { accg[i][j] = 0.0; accu[i][j] = 0.0; }

    for (int kt = 0; kt < DIM; kt += BKK) {
#pragma unroll
        for (int it = 0; it < 2; it++) {
            float4 v = *(const float4*)(arow_ptr[it] + kt + ac4);
            int r = arow0 + it * 64;
            As[ac4 + 0][r] = v.x; As[ac4 + 1][r] = v.y;
            As[ac4 + 2][r] = v.z; As[ac4 + 3][r] = v.w;
        }
#pragma unroll
        for (int it = 0; it < 2; it++) {
            int br = brow0 + it * 8;
            size_t off = (size_t)(kt + br) * N + (size_t)ntile * BN + bc;
            *(float4*)&Bgs[br][bc] = *(const float4*)(Wg + off);
            *(float4*)&Bus[br][bc] = *(const float4*)(Wu + off);
        }
        __syncthreads();
#pragma unroll
        for (int kk = 0; kk < BKK; kk++) {
            float a[TM];
            float4 a0 = *(const float4*)&As[kk][ty * TM];
            float4 a1 = *(const float4*)&As[kk][ty * TM + 4];
            a[0] = a0.x; a[1] = a0.y; a[2] = a0.z; a[3] = a0.w;
            a[4] = a1.x; a[5] = a1.y; a[6] = a1.z; a[7] = a1.w;
            double bg[4], bu[4];
            double2 g0 = *(const double2*)&Bgs[kk][tx * TN];
            double2 g1 = *(const double2*)&Bgs[kk][tx * TN + 4];
            bg[0] = g0.x; bg[1] = g0.y; bg[2] = g1.x; bg[3] = g1.y;
            double2 u0 = *(const double2*)&Bus[kk][tx * TN];
            double2 u1 = *(const double2*)&Bus[kk][tx * TN + 4];
            bu[0] = u0.x; bu[1] = u0.y; bu[2] = u1.x; bu[3] = u1.y;
#pragma unroll
            for (int i = 0; i < TM; i++) {
                double a2 = dup2(a[i]);
#pragma unroll
                for (int j = 0; j < TN / 2; j++) {
                    accg[i][j] = ffma2(a2, bg[j], accg[i][j]);
                    accu[i][j] = ffma2(a2, bu[j], accu[i][j]);
                }
            }
        }
        __syncthreads();
    }

    // epilogue
#pragma unroll
    for (int i = 0; i < TM; i++) {
        int rloc = ty * TM + i;
        int rglb = mtile * BM + rloc;
        if (ROUTED && rglb >= Me) continue;
        float w = 1.0f;
        float* orow;
        if (ROUTED) {
            int slot = start + rglb;
            w = g_slot_w[slot];
            orow = g_hbuf + (size_t)slot * N + (size_t)ntile * BN + tx * TN;
        } else {
            orow = g_sh + (size_t)rglb * N + (size_t)ntile * BN + tx * TN;
        }
#pragma unroll
        for (int j = 0; j < TN / 2; j++) {
            float2 g = unpack2(accg[i][j]);
            float2 u = unpack2(accu[i][j]);
            float2 h;
            h.x = silu_f(g.x) * u.x * w;
            h.y = silu_f(g.y) * u.y * w;
            *(float2*)&orow[2 * j] = h;
        }
    }
}

// ---------------- down-projection GEMM ----------------
// ROUTED: A = g_hbuf (by slot), epilogue atomicAdd into out[token].
// !ROUTED: A = g_sh (dense), epilogue plain store (initializes out).
template <bool ROUTED>
__global__ __launch_bounds__(NTHREADS, 1)
void down_kernel(const float* __restrict__ Wd,
                 float* __restrict__ Out,
                 int K)  // HDIM (routed) or HSDIM (shared)
{
    int mtile = blockIdx.y, ntile = blockIdx.x;
    int expert = 0, start = 0, Me = T_TOKENS;
    if (ROUTED) {
        expert = blockIdx.z;
        start = g_offsets[expert];
        Me = g_offsets[expert + 1] - start;
        if (mtile * BM >= Me) return;
        Wd += (size_t)expert * K * DIM;
    }
    const float* Abase = ROUTED ? g_hbuf : g_sh;

    __shared__ float As[BKK][BM + 4];
    __shared__ float Bs[BKK][BN];

    int tid = threadIdx.x;
    int tx = tid & 15, ty = tid >> 4;

    int arow0 = tid >> 2;
    int ac4 = (tid & 3) * 4;
    const float* arow_ptr[2];
#pragma unroll
    for (int it = 0; it < 2; it++) {
        int r = arow0 + it * 64;
        int rr = mtile * BM + r;
        if (rr >= Me) rr = Me - 1;
        size_t row = ROUTED ? (size_t)(start + rr) : (size_t)rr;
        arow_ptr[it] = Abase + row * K;
    }
    int brow0 = tid >> 5;
    int bc = (tid & 31) * 4;

    double acc[TM][TN / 2];
#pragma unroll
    for (int i = 0; i < TM; i++)
#pragma unroll
        for (int j = 0; j < TN / 2; j++) acc[i][j] = 0.0;

    for (int kt = 0; kt < K; kt += BKK) {
#pragma unroll
        for (int it = 0; it < 2; it++) {
            float4 v = *(const float4*)(arow_ptr[it] + kt + ac4);
            int r = arow0 + it * 64;
            As[ac4 + 0][r] = v.x; As[ac4 + 1][r] = v.y;
            As[ac4 + 2][r] = v.z; As[ac4 + 3][r] = v.w;
        }
#pragma unroll
        for (int it = 0; it < 2; it++) {
            int br = brow0 + it * 8;
            size_t off = (size_t)(kt + br) * DIM + (size_t)ntile * BN + bc;
            *(float4*)&Bs[br][bc] = *(const float4*)(Wd + off);
        }
        __syncthreads();
#pragma unroll
        for (int kk = 0; kk < BKK; kk++) {
            float a[TM];
            float4 a0 = *(const float4*)&As[kk][ty * TM];
            float4 a1 = *(const float4*)&As[kk][ty * TM + 4];
            a[0] = a0.x; a[1] = a0.y; a[2] = a0.z; a[3] = a0.w;
            a[4] = a1.x; a[5] = a1.y; a[6] = a1.z; a[7] = a1.w;
            double b[4];
            double2 b0 = *(const double2*)&Bs[kk][tx * TN];
            double2 b1 = *(const double2*)&Bs[kk][tx * TN + 4];
            b[0] = b0.x; b[1] = b0.y; b[2] = b1.x; b[3] = b1.y;
#pragma unroll
            for (int i = 0; i < TM; i++) {
                double a2 = dup2(a[i]);
#pragma unroll
                for (int j = 0; j < TN / 2; j++)
                    acc[i][j] = ffma2(a2, b[j], acc[i][j]);
            }
        }
        __syncthreads();
    }

    int colbase = ntile * BN + tx * TN;
#pragma unroll
    for (int i = 0; i < TM; i++) {
        int rloc = ty * TM + i;
        int rglb = mtile * BM + rloc;
        if (ROUTED) {
            if (rglb >= Me) continue;
            int token = g_slot_token[start + rglb];
            float* dst = Out + (size_t)token * DIM + colbase;
#pragma unroll
            for (int j = 0; j < TN / 2; j++) {
                float2 v = unpack2(acc[i][j]);
                atomicAdd(&dst[2 * j], v.x);
                atomicAdd(&dst[2 * j + 1], v.y);
            }
        } else {
            float* dst = Out + (size_t)rglb * DIM + colbase;
#pragma unroll
            for (int j = 0; j < TN / 2; j++) {
                float2 v = unpack2(acc[i][j]);
                *(float2*)&dst[2 * j] = v;
            }
        }
    }
}

// ---------------- launch ----------------
extern "C" void kernel_launch(void* const* d_in, const int* in_sizes, int n_in,
                              void* d_out, int out_size) {
    const float* x   = (const float*)d_in[0];
    const float* rw  = (const float*)d_in[1];
    const float* wg  = (const float*)d_in[2];
    const float* wu  = (const float*)d_in[3];
    const float* wd  = (const float*)d_in[4];
    const float* swg = (const float*)d_in[5];
    const float* swu = (const float*)d_in[6];
    const float* swd = (const float*)d_in[7];
    float* out = (float*)d_out;

    zero_small_kernel<<<1, 32>>>();
    router_kernel<<<T_TOKENS / 8, 256>>>(x, rw);
    scan_kernel<<<1, 32>>>();
    scatter_kernel<<<NSLOTS / 256, 256>>>();

    // shared expert: gate/up then down (down initializes out with plain stores)
    gateup_kernel<false><<<dim3(HSDIM / BN, T_TOKENS / BM, 1), NTHREADS>>>(x, swg, swu, HSDIM);
    down_kernel<false><<<dim3(DIM / BN, T_TOKENS / BM, 1), NTHREADS>>>(swd, out, HSDIM);

    // routed experts: grouped gate/up (gather + weight fold) then down (atomicAdd)
    gateup_kernel<true><<<dim3(HDIM / BN, NSLOTS / BM, NEXP), NTHREADS>>>(x, wg, wu, HDIM);
    down_kernel<true><<<dim3(DIM / BN, NSLOTS / BM, NEXP), NTHREADS>>>(wd, out, HDIM);
}